// round 7
// baseline (speedup 1.0000x reference)
#include <cuda_runtime.h>

// E[b] = sum over strict-lower-tri pairs (i,j) (row-major flat order):
//          decompFE_flat[b,p] * rsqrt(|coords[b,i]-coords[b,j]|^2)
//
// jblk-major, lane-resident j coords. Single merged loop per jblk with a
// per-row lane mask (no partial/full split). Smem coords interleaved
// [atom][batch][4] so one address serves both batches (imm-offset LDS.128).
// Flat offset maintained incrementally; batch-1 gmem load folds to LDG imm.

#define BATCH   2048
#define NATOMS  100
#define NC2     4950
#define TPB     256
#define NWARPS  (TPB / 32)
#define BPB     2

__global__ __launch_bounds__(TPB, 7)
void eij_kernel(const float* __restrict__ coords,
                const float* __restrict__ flat,
                float* __restrict__ out)
{
    // sc[atom][q][4]: float4-aligned per (atom,q)
    __shared__ float sc[NATOMS * BPB * 4];
    __shared__ float warp_part[BPB][NWARPS];

    const int b0   = blockIdx.x * BPB;
    const int t    = threadIdx.x;
    const int lane = t & 31;
    const int wid  = t >> 5;

    // stage coords interleaved: sc[atom*8 + q*4 + c]
    for (int k = t; k < NATOMS * 3 * BPB; k += TPB) {
        const int q    = k / (NATOMS * 3);
        const int r    = k - q * (NATOMS * 3);
        const int atom = r / 3;
        const int c    = r - atom * 3;
        sc[atom * (BPB * 4) + q * 4 + c] =
            coords[(size_t)(b0 + q) * (NATOMS * 3) + r];
    }
    __syncthreads();

    const float* fb = flat + (size_t)b0 * NC2;

    float acc0 = 0.0f, acc1 = 0.0f;

    #pragma unroll
    for (int jb = 0; jb < 4; ++jb) {
        const int jbase = jb * 32;
        const int j = jbase + lane;

        float xj0 = 0.f, yj0 = 0.f, zj0 = 0.f;
        float xj1 = 0.f, yj1 = 0.f, zj1 = 0.f;
        if (j < NATOMS) {
            const float4 c0 = *(const float4*)&sc[j * 8 + 0];
            const float4 c1 = *(const float4*)&sc[j * 8 + 4];
            xj0 = c0.x; yj0 = c0.y; zj0 = c0.z;
            xj1 = c1.x; yj1 = c1.y; zj1 = c1.z;
        }

        // merged loop over all rows for this jblk (mask handles diagonal band)
        int i   = jbase + 1 + wid;
        int off = i * (i - 1) / 2 + jbase + lane;

        #pragma unroll 4
        for (; i < NATOMS; i += NWARPS, off += 8 * i - 36) { // 8*(i_old)+28
            const bool valid = lane < (i - jbase);

            float v0 = 0.0f, v1 = 0.0f;
            if (valid) {
                const float* p = fb + off;
                v0 = __ldcs(p);
                v1 = __ldcs(p + NC2);
            }

            const float4 ci0 = *(const float4*)&sc[i * 8 + 0];
            const float4 ci1 = *(const float4*)&sc[i * 8 + 4];

            float dx0 = ci0.x - xj0, dy0 = ci0.y - yj0, dz0 = ci0.z - zj0;
            float dx1 = ci1.x - xj1, dy1 = ci1.y - yj1, dz1 = ci1.z - zj1;
            float r20 = fmaf(dx0, dx0, fmaf(dy0, dy0, dz0 * dz0));
            float r21 = fmaf(dx1, dx1, fmaf(dy1, dy1, dz1 * dz1));

            if (valid) {
                acc0 = fmaf(v0, rsqrtf(r20), acc0);
                acc1 = fmaf(v1, rsqrtf(r21), acc1);
            }
        }
    }

    // reductions
    #pragma unroll
    for (int off = 16; off > 0; off >>= 1) {
        acc0 += __shfl_down_sync(0xFFFFFFFFu, acc0, off);
        acc1 += __shfl_down_sync(0xFFFFFFFFu, acc1, off);
    }
    if (lane == 0) { warp_part[0][wid] = acc0; warp_part[1][wid] = acc1; }
    __syncthreads();

    if (wid == 0 && lane < NWARPS) {
        float s0 = warp_part[0][lane];
        float s1 = warp_part[1][lane];
        #pragma unroll
        for (int off = NWARPS / 2; off > 0; off >>= 1) {
            s0 += __shfl_down_sync(0xFFu, s0, off);
            s1 += __shfl_down_sync(0xFFu, s1, off);
        }
        if (lane == 0) { out[b0] = s0; out[b0 + 1] = s1; }
    }
}

extern "C" void kernel_launch(void* const* d_in, const int* in_sizes, int n_in,
                              void* d_out, int out_size)
{
    const float* coords = (const float*)d_in[0];   // [2048, 100, 3]
    const float* flat   = (const float*)d_in[1];   // [2048, 4950]
    float* out          = (float*)d_out;           // [2048, 1]

    eij_kernel<<<BATCH / BPB, TPB>>>(coords, flat, out);
}